// round 6
// baseline (speedup 1.0000x reference)
#include <cuda_runtime.h>
#include <math.h>
#include <stdint.h>

#define KT 64
#define VV 50000
#define DD 128
#define BB 8192
#define LL 126
#define BOS 62
#define EOS 63

typedef unsigned long long ull;

// Scratch (static __device__ — no allocations allowed)
__device__ float g_A[KT * KT];          // raw transition probs (row softmax of WA, col BOS = 0)
__device__ float g_As[KT * KT];         // invZ-folded + column-permuted A for forward pass
__device__ float g_Z[KT];               // per-tag emission partition sums
__device__ float g_Bt[(size_t)VV * KT]; // exp(theta_k . E_v), layout [v][k] (256B rows)

// ---- packed f32x2 helpers ----------------------------------------------------
__device__ __forceinline__ ull fma2(ull a, ull b, ull c) {
    ull d;
    asm("fma.rn.f32x2 %0, %1, %2, %3;" : "=l"(d) : "l"(a), "l"(b), "l"(c));
    return d;
}
__device__ __forceinline__ ull mul2(ull a, ull b) {
    ull d;
    asm("mul.rn.f32x2 %0, %1, %2;" : "=l"(d) : "l"(a), "l"(b));
    return d;
}
__device__ __forceinline__ ull packdup(float x) {
    ull d;
    asm("mov.b64 %0, {%1, %1};" : "=l"(d) : "f"(x));
    return d;
}
__device__ __forceinline__ void unpack2(ull v, float& lo, float& hi) {
    asm("mov.b64 {%0, %1}, %2;" : "=f"(lo), "=f"(hi) : "l"(v));
}

// ---------------------------------------------------------------------------
// Kernel 1: transition softmax + zero Z accumulators
// ---------------------------------------------------------------------------
__global__ void k_trans(const float* __restrict__ WA) {
    __shared__ float w[KT * KT];
    for (int idx = threadIdx.x; idx < KT * KT; idx += 256) w[idx] = WA[idx];
    __syncthreads();
    int i = threadIdx.x;
    if (i < KT) {
        float m = -1e30f;
        for (int j = 0; j < KT; j++)
            if (j != BOS) m = fmaxf(m, w[i * KT + j]);
        float ssum = 0.f;
        for (int j = 0; j < KT; j++)
            if (j != BOS) ssum += __expf(w[i * KT + j] - m);
        float inv = 1.f / ssum;
        for (int j = 0; j < KT; j++)
            g_A[i * KT + j] = (j == BOS) ? 0.f : __expf(w[i * KT + j] - m) * inv;
        g_Z[i] = 0.f;
    }
}

// ---------------------------------------------------------------------------
// Kernel 2: emission table  g_Bt[v][k] = exp(theta_k . E_v), accumulate Z[k].
// Block = 256 threads = 64 tags x 4 v-groups; block covers 64 v's.
// theta in smem [64][33] float4 (stride 33 -> conflict-free column reads);
// E rows read via broadcast __ldg float4 (all 32 lanes of a warp share v).
// 4-v register blocking: per d4-step 1 LDS.128 + 4 LDG.128 + 16 FMA.
// Z reduced in smem across v-groups, one atomicAdd per tag per block.
// VV % 64 == 16, so validity is uniform per v-group slice (no per-elem guard).
// ---------------------------------------------------------------------------
__global__ void __launch_bounds__(256) k_emit(const float* __restrict__ ThetaB,
                                              const float* __restrict__ E) {
    __shared__ __align__(16) float4 th4s[KT][33];
    __shared__ float zsh[4][KT];
    int tid = threadIdx.x;
    int k  = tid & 63;
    int vg = tid >> 6;
    for (int idx = tid; idx < KT * DD / 4; idx += 256) {
        int kk = idx >> 5, d4 = idx & 31;
        th4s[kk][d4] = ((const float4*)ThetaB)[idx];
    }
    __syncthreads();

    float zacc = 0.f;
    int vbase = blockIdx.x * 64 + vg * 16;
    if (vbase < VV) {
#pragma unroll
        for (int vc = 0; vc < 4; vc++) {
            int v0 = vbase + vc * 4;
            const float4* E0 = (const float4*)(E + (size_t)(v0 + 0) * DD);
            const float4* E1 = (const float4*)(E + (size_t)(v0 + 1) * DD);
            const float4* E2 = (const float4*)(E + (size_t)(v0 + 2) * DD);
            const float4* E3 = (const float4*)(E + (size_t)(v0 + 3) * DD);
            float d0a = 0.f, d0b = 0.f, d1a = 0.f, d1b = 0.f;
            float d2a = 0.f, d2b = 0.f, d3a = 0.f, d3b = 0.f;
#pragma unroll 8
            for (int d4 = 0; d4 < DD / 4; d4++) {
                float4 t = th4s[k][d4];
                float4 a = __ldg(E0 + d4);
                float4 b = __ldg(E1 + d4);
                float4 c = __ldg(E2 + d4);
                float4 d = __ldg(E3 + d4);
                d0a = fmaf(t.x, a.x, fmaf(t.y, a.y, d0a));
                d0b = fmaf(t.z, a.z, fmaf(t.w, a.w, d0b));
                d1a = fmaf(t.x, b.x, fmaf(t.y, b.y, d1a));
                d1b = fmaf(t.z, b.z, fmaf(t.w, b.w, d1b));
                d2a = fmaf(t.x, c.x, fmaf(t.y, c.y, d2a));
                d2b = fmaf(t.z, c.z, fmaf(t.w, c.w, d2b));
                d3a = fmaf(t.x, d.x, fmaf(t.y, d.y, d3a));
                d3b = fmaf(t.z, d.z, fmaf(t.w, d.w, d3b));
            }
            float p0 = __expf(d0a + d0b);
            float p1 = __expf(d1a + d1b);
            float p2 = __expf(d2a + d2b);
            float p3 = __expf(d3a + d3b);
            g_Bt[(size_t)(v0 + 0) * KT + k] = p0;
            g_Bt[(size_t)(v0 + 1) * KT + k] = p1;
            g_Bt[(size_t)(v0 + 2) * KT + k] = p2;
            g_Bt[(size_t)(v0 + 3) * KT + k] = p3;
            zacc += (p0 + p1) + (p2 + p3);
        }
    }
    zsh[vg][k] = zacc;
    __syncthreads();
    if (vg == 0)
        atomicAdd(&g_Z[k], (zsh[0][k] + zsh[1][k]) + (zsh[2][k] + zsh[3][k]));
}

// ---------------------------------------------------------------------------
// Kernel 3: fold invZ into A's columns + permute columns for conflict-free
// forward loads. Column j (gq=j>>3, m=j&7) -> pos = m<4 ? 4gq+m : 32+4gq+m-4.
// BOS/EOS columns get invZ=0 (emission prob 0 there).
// ---------------------------------------------------------------------------
__global__ void __launch_bounds__(256) k_scaleA() {
    int idx = blockIdx.x * 256 + threadIdx.x;
    if (idx < KT * KT) {
        int i = idx >> 6, j = idx & 63;
        float iz = (j >= BOS) ? 0.f : (1.f / g_Z[j]);
        int gq = j >> 3, m = j & 7;
        int pos = (m < 4) ? (gq * 4 + m) : (32 + gq * 4 + (m - 4));
        g_As[i * KT + pos] = g_A[i * KT + j] * iz;
    }
}

// ---------------------------------------------------------------------------
// Kernel 4: forward recursion, scaled-probability domain, packed f32x2 FMA.
// Block = 64 threads = 2 warps sharing read-only Ash. Grid = 512
// (-> ~6.9 warps/SM: enough to hide LDS latency and saturate the fma pipe).
// Warp: lane = 4*g + ss; g=0..7 owns tags 8g..8g+7; ss=0..3; C=2 sentences
// per lane -> 8 sentences/warp, 16/block.
// Per prev-tag i: 2 LDS.128 (A, conflict-free via column permutation) +
// 2 LDS.64 (duplicated p, broadcast) + 8 fma.rn.f32x2.
// Power-of-two rescale every 2 steps (min shrink/step ~2^-25 -> safe).
// ---------------------------------------------------------------------------
__global__ void __launch_bounds__(64) k_forward(const int* __restrict__ words,
                                                float* __restrict__ out) {
    __shared__ __align__(16) float Ash[KT][KT];
    __shared__ ull pd[2][2][KT][9];   // [warp][buf][rowp][sent] duplicated pairs
    int tid  = threadIdx.x;
    int wid  = tid >> 5;
    int lane = tid & 31;
    int g    = lane >> 2;   // tag group
    int ss   = lane & 3;    // sentence slot

    for (int idx = tid; idx < KT * KT / 4; idx += 64)
        ((float4*)Ash)[idx] = ((const float4*)g_As)[idx];
    __syncthreads();

    int sbase = blockIdx.x * 16 + wid * 8;
    const int* wp0 = words + (size_t)(sbase + 2 * ss + 0) * LL;
    const int* wp1 = words + (size_t)(sbase + 2 * ss + 1) * LL;

    // initial p: one-hot at BOS tag (62 = 8*7+6 -> g==7, r==6)
#pragma unroll
    for (int r = 0; r < 8; r++) {
        ull pv = packdup((g == 7 && r == 6) ? 1.f : 0.f);
        pd[wid][0][8 * r + g][2 * ss + 0] = pv;
        pd[wid][0][8 * r + g][2 * ss + 1] = pv;
    }
    __syncwarp();

    int w0 = wp0[0], w1 = wp1[0];
    int S0 = 0, S1 = 0;
    int buf = 0;
    float f[8][2];

    for (int step = 0; step < LL; step++) {
        // this step's emission rows (L2 latency hidden by the mat-vec below)
        ull ee0[4], ee1[4];
        {
            const ulonglong2* e0 = (const ulonglong2*)(g_Bt + (size_t)w0 * KT + g * 8);
            const ulonglong2* e1 = (const ulonglong2*)(g_Bt + (size_t)w1 * KT + g * 8);
            ulonglong2 ta = e0[0], tb = e0[1], tc = e1[0], td = e1[1];
            ee0[0] = ta.x; ee0[1] = ta.y; ee0[2] = tb.x; ee0[3] = tb.y;
            ee1[0] = tc.x; ee1[1] = tc.y; ee1[2] = td.x; ee1[3] = td.y;
        }
        if (step < LL - 1) { w0 = wp0[step + 1]; w1 = wp1[step + 1]; }

        // q = A^T p  (packed over adjacent tag pairs), 2 sentences
        ull q0[4], q1[4];
#pragma unroll
        for (int pp = 0; pp < 4; pp++) { q0[pp] = 0ull; q1[pp] = 0ull; }

#pragma unroll
        for (int i = 0; i < KT; i++) {
            const float* ar = Ash[i];
            ulonglong2 a0 = *(const ulonglong2*)(ar + 4 * g);        // tags 8g..8g+3
            ulonglong2 a1 = *(const ulonglong2*)(ar + 32 + 4 * g);   // tags 8g+4..8g+7
            int rp = ((i & 7) << 3) + (i >> 3);
            ull p0 = pd[wid][buf][rp][2 * ss + 0];
            ull p1 = pd[wid][buf][rp][2 * ss + 1];
            q0[0] = fma2(a0.x, p0, q0[0]);
            q0[1] = fma2(a0.y, p0, q0[1]);
            q0[2] = fma2(a1.x, p0, q0[2]);
            q0[3] = fma2(a1.y, p0, q0[3]);
            q1[0] = fma2(a0.x, p1, q1[0]);
            q1[1] = fma2(a0.y, p1, q1[1]);
            q1[2] = fma2(a1.x, p1, q1[2]);
            q1[3] = fma2(a1.y, p1, q1[3]);
        }

        // p' = q * em (invZ folded into A)
#pragma unroll
        for (int pp = 0; pp < 4; pp++) {
            unpack2(mul2(q0[pp], ee0[pp]), f[2 * pp][0], f[2 * pp + 1][0]);
            unpack2(mul2(q1[pp], ee1[pp]), f[2 * pp][1], f[2 * pp + 1][1]);
        }

        if ((step & 1) == 1) {      // power-of-two rescale every 2 steps
            float pm0 = 0.f, pm1 = 0.f;
#pragma unroll
            for (int r = 0; r < 8; r++) {
                pm0 = fmaxf(pm0, f[r][0]);
                pm1 = fmaxf(pm1, f[r][1]);
            }
            pm0 = fmaxf(pm0, __shfl_xor_sync(0xffffffffu, pm0, 4));
            pm0 = fmaxf(pm0, __shfl_xor_sync(0xffffffffu, pm0, 8));
            pm0 = fmaxf(pm0, __shfl_xor_sync(0xffffffffu, pm0, 16));
            pm1 = fmaxf(pm1, __shfl_xor_sync(0xffffffffu, pm1, 4));
            pm1 = fmaxf(pm1, __shfl_xor_sync(0xffffffffu, pm1, 8));
            pm1 = fmaxf(pm1, __shfl_xor_sync(0xffffffffu, pm1, 16));
            int e0i = 0, e1i = 0;
            if (pm0 > 0.f) e0i = ((__float_as_int(pm0) >> 23) & 255) - 126;
            if (pm1 > 0.f) e1i = ((__float_as_int(pm1) >> 23) & 255) - 126;
            S0 += e0i; S1 += e1i;
            float sc0 = __int_as_float((127 - e0i) << 23);
            float sc1 = __int_as_float((127 - e1i) << 23);
#pragma unroll
            for (int r = 0; r < 8; r++) { f[r][0] *= sc0; f[r][1] *= sc1; }
        }

        int nb = buf ^ 1;
#pragma unroll
        for (int r = 0; r < 8; r++) {
            pd[wid][nb][8 * r + g][2 * ss + 0] = packdup(f[r][0]);
            pd[wid][nb][8 * r + g][2 * ss + 1] = packdup(f[r][1]);
        }
        buf = nb;
        __syncwarp();
    }

    // final transition into EOS using the UNSCALED A column
    float aeos[8];
#pragma unroll
    for (int r = 0; r < 8; r++) aeos[r] = g_A[(8 * g + r) * KT + EOS];
    float part0 = 0.f, part1 = 0.f;
#pragma unroll
    for (int r = 0; r < 8; r++) {
        part0 = fmaf(f[r][0], aeos[r], part0);
        part1 = fmaf(f[r][1], aeos[r], part1);
    }
    part0 += __shfl_xor_sync(0xffffffffu, part0, 4);
    part0 += __shfl_xor_sync(0xffffffffu, part0, 8);
    part0 += __shfl_xor_sync(0xffffffffu, part0, 16);
    part1 += __shfl_xor_sync(0xffffffffu, part1, 4);
    part1 += __shfl_xor_sync(0xffffffffu, part1, 8);
    part1 += __shfl_xor_sync(0xffffffffu, part1, 16);
    if (g == 0) {
        out[sbase + 2 * ss + 0] = __logf(part0) + (float)S0 * 0.6931471805599453f;
        out[sbase + 2 * ss + 1] = __logf(part1) + (float)S1 * 0.6931471805599453f;
    }
}

// ---------------------------------------------------------------------------
extern "C" void kernel_launch(void* const* d_in, const int* in_sizes, int n_in,
                              void* d_out, int out_size) {
    const int* words = nullptr;
    const float* ThetaB = nullptr;
    const float* WA = nullptr;
    const float* E = nullptr;
    for (int i = 0; i < n_in; i++) {
        switch (in_sizes[i]) {
            case BB * LL:   words  = (const int*)d_in[i];   break;
            case KT * DD:   ThetaB = (const float*)d_in[i]; break;
            case KT * KT:   WA     = (const float*)d_in[i]; break;
            case VV * DD:   E      = (const float*)d_in[i]; break;
            default: break;
        }
    }

    k_trans<<<1, 256>>>(WA);
    k_emit<<<(VV + 63) / 64, 256>>>(ThetaB, E);
    k_scaleA<<<16, 256>>>();
    k_forward<<<BB / 16, 64>>>(words, (float*)d_out);
}

// round 8
// speedup vs baseline: 1.0865x; 1.0865x over previous
#include <cuda_runtime.h>
#include <math.h>
#include <stdint.h>

#define KT 64
#define VV 50000
#define DD 128
#define BB 8192
#define LL 126
#define BOS 62
#define EOS 63
#define FOLD 32768.0f          // 2^15 folded into scaled A (anti-underflow)
#define FOLD_LOG2 15

typedef unsigned long long ull;

// Scratch (static __device__ — no allocations allowed)
__device__ float g_A[KT * KT];           // raw transition probs (row softmax of WA, col BOS = 0)
__device__ float g_Ast[KT * KT];         // transposed: g_Ast[j*64+i] = A[i][j] * invZ[j] * 2^15
__device__ float g_Z[KT];                // per-tag emission partition sums
__device__ float g_Bt[(size_t)VV * KT];  // exp(theta_k . E_v), layout [v][k] (256B rows)

// ---- packed f32x2 helpers ---------------------------------------------------
__device__ __forceinline__ ull fma2(ull a, ull b, ull c) {
    ull d;
    asm("fma.rn.f32x2 %0, %1, %2, %3;" : "=l"(d) : "l"(a), "l"(b), "l"(c));
    return d;
}
__device__ __forceinline__ ull mul2(ull a, ull b) {
    ull d;
    asm("mul.rn.f32x2 %0, %1, %2;" : "=l"(d) : "l"(a), "l"(b));
    return d;
}
__device__ __forceinline__ ull packdup(float x) {
    ull d;
    asm("mov.b64 %0, {%1, %1};" : "=l"(d) : "f"(x));
    return d;
}
__device__ __forceinline__ ull pack2(float lo, float hi) {
    ull d;
    asm("mov.b64 %0, {%1, %2};" : "=l"(d) : "f"(lo), "f"(hi));
    return d;
}
__device__ __forceinline__ void unpack2(ull v, float& lo, float& hi) {
    asm("mov.b64 {%0, %1}, %2;" : "=f"(lo), "=f"(hi) : "l"(v));
}

// ---------------------------------------------------------------------------
// Kernel 1: transition softmax + zero Z accumulators
// ---------------------------------------------------------------------------
__global__ void k_trans(const float* __restrict__ WA) {
    __shared__ float w[KT * KT];
    for (int idx = threadIdx.x; idx < KT * KT; idx += 256) w[idx] = WA[idx];
    __syncthreads();
    int i = threadIdx.x;
    if (i < KT) {
        float m = -1e30f;
        for (int j = 0; j < KT; j++)
            if (j != BOS) m = fmaxf(m, w[i * KT + j]);
        float ssum = 0.f;
        for (int j = 0; j < KT; j++)
            if (j != BOS) ssum += __expf(w[i * KT + j] - m);
        float inv = 1.f / ssum;
        for (int j = 0; j < KT; j++)
            g_A[i * KT + j] = (j == BOS) ? 0.f : __expf(w[i * KT + j] - m) * inv;
        g_Z[i] = 0.f;
    }
}

// ---------------------------------------------------------------------------
// Kernel 2: emission table  g_Bt[v][k] = exp(theta_k . E_v), accumulate Z[k].
// Both fma2 operands packed over d-pairs (no dup movs): theta staged in smem
// transposed as u64 d-pairs thsh[d2][k] (lane-consecutive -> conflict-free),
// E rows read as broadcast ulonglong2. 14 instr / 16 MAC inner loop.
// ---------------------------------------------------------------------------
__global__ void __launch_bounds__(256) k_emit(const float* __restrict__ ThetaB,
                                              const float* __restrict__ E) {
    __shared__ ull thsh[DD / 2][KT];     // [d2][k] = (theta[k][2*d2], theta[k][2*d2+1])
    __shared__ float zsh[4][KT];
    int tid = threadIdx.x;
    int k  = tid & 63;
    int vg = tid >> 6;
    for (int idx = tid; idx < KT * DD / 2; idx += 256) {
        int kk = idx >> 6, d2 = idx & 63;
        thsh[d2][kk] = ((const ull*)ThetaB)[kk * (DD / 2) + d2];
    }
    __syncthreads();

    float zacc = 0.f;
    int vbase = blockIdx.x * 64 + vg * 16;
    if (vbase < VV) {
#pragma unroll
        for (int vc = 0; vc < 4; vc++) {
            int v0 = vbase + vc * 4;
            const ulonglong2* E0 = (const ulonglong2*)(E + (size_t)(v0 + 0) * DD);
            const ulonglong2* E1 = (const ulonglong2*)(E + (size_t)(v0 + 1) * DD);
            const ulonglong2* E2 = (const ulonglong2*)(E + (size_t)(v0 + 2) * DD);
            const ulonglong2* E3 = (const ulonglong2*)(E + (size_t)(v0 + 3) * DD);
            ull a0 = 0, a1 = 0, b0 = 0, b1 = 0, c0 = 0, c1 = 0, d0 = 0, d1 = 0;
#pragma unroll 8
            for (int d4 = 0; d4 < DD / 4; d4++) {
                ull t0 = thsh[2 * d4][k];
                ull t1 = thsh[2 * d4 + 1][k];
                ulonglong2 ea = __ldg(E0 + d4);
                ulonglong2 eb = __ldg(E1 + d4);
                ulonglong2 ec = __ldg(E2 + d4);
                ulonglong2 ed = __ldg(E3 + d4);
                a0 = fma2(t0, ea.x, a0); a1 = fma2(t1, ea.y, a1);
                b0 = fma2(t0, eb.x, b0); b1 = fma2(t1, eb.y, b1);
                c0 = fma2(t0, ec.x, c0); c1 = fma2(t1, ec.y, c1);
                d0 = fma2(t0, ed.x, d0); d1 = fma2(t1, ed.y, d1);
            }
            float x0, x1, y0, y1;
            unpack2(a0, x0, x1); unpack2(a1, y0, y1);
            float p0 = __expf((x0 + y0) + (x1 + y1));
            unpack2(b0, x0, x1); unpack2(b1, y0, y1);
            float p1 = __expf((x0 + y0) + (x1 + y1));
            unpack2(c0, x0, x1); unpack2(c1, y0, y1);
            float p2 = __expf((x0 + y0) + (x1 + y1));
            unpack2(d0, x0, x1); unpack2(d1, y0, y1);
            float p3 = __expf((x0 + y0) + (x1 + y1));
            g_Bt[(size_t)(v0 + 0) * KT + k] = p0;
            g_Bt[(size_t)(v0 + 1) * KT + k] = p1;
            g_Bt[(size_t)(v0 + 2) * KT + k] = p2;
            g_Bt[(size_t)(v0 + 3) * KT + k] = p3;
            zacc += (p0 + p1) + (p2 + p3);
        }
    }
    zsh[vg][k] = zacc;
    __syncthreads();
    if (vg == 0)
        atomicAdd(&g_Z[k], (zsh[0][k] + zsh[1][k]) + (zsh[2][k] + zsh[3][k]));
}

// ---------------------------------------------------------------------------
// Kernel 3: build g_Ast[j*64+i] = A[i][j] * invZ[j] * 2^15 (transposed so a
// forward thread loads its column contiguously). BOS/EOS columns -> 0.
// ---------------------------------------------------------------------------
__global__ void __launch_bounds__(256) k_scaleA() {
    int idx = blockIdx.x * 256 + threadIdx.x;
    if (idx < KT * KT) {
        int i = idx >> 6, j = idx & 63;
        float iz = (j >= BOS) ? 0.f : (FOLD / g_Z[j]);
        g_Ast[j * KT + i] = g_A[i * KT + j] * iz;
    }
}

// ---------------------------------------------------------------------------
// Kernel 4: forward recursion. Block = 64 threads; thread j owns transition
// column j IN REGISTERS (a[64], invZ+2^15 folded). 16 sentences per block as
// 8 packed pairs; grid 512 -> ~6.9 warps/SM. Per i-pair: 2 dup movs
// (amortized over 8 pairs) + 8 broadcast LDS.128 (p, [sp][i] layout,
// conflict-free) + 16 fma.rn.f32x2. Stores conflict-free (consecutive u64).
// Exact per-sentence power-of-two rescale every 16 steps (2^15 fold keeps p
// in range between rescales); final compensation (S - 126*15)*ln2.
// ---------------------------------------------------------------------------
__global__ void __launch_bounds__(64) k_forward(const int* __restrict__ words,
                                                float* __restrict__ out) {
    __shared__ __align__(16) ull ps[2][8][KT];  // [buf][sent-pair][prev-tag]
    __shared__ int wflat[16 * LL];
    __shared__ float2 exch[2][8];
    int tid = threadIdx.x;
    int w   = tid >> 5;
    int l   = tid & 31;
    int j   = tid;            // owned column/tag

    // A column into registers (contiguous row of g_Ast)
    float a[KT];
    {
        const float4* ar = (const float4*)(g_Ast + j * KT);
#pragma unroll
        for (int t = 0; t < 16; t++) {
            float4 v = ar[t];
            a[4 * t] = v.x; a[4 * t + 1] = v.y; a[4 * t + 2] = v.z; a[4 * t + 3] = v.w;
        }
    }
    float aeos = g_A[j * KT + EOS];

    int sbase = blockIdx.x * 16;
    const int* wsrc = words + (size_t)sbase * LL;
    for (int idx = tid; idx < 16 * LL; idx += 64) wflat[idx] = wsrc[idx];

    // initial p: one-hot at BOS (duplicated pair)
    for (int idx = tid; idx < 8 * KT; idx += 64) {
        int i = idx & 63;
        ps[0][idx >> 6][i] = (i == BOS) ? packdup(1.f) : 0ull;
    }
    __syncthreads();

    int S[16];
#pragma unroll
    for (int c = 0; c < 16; c++) S[c] = 0;
    int buf = 0;
    ull pn[8];

    for (int step = 0; step < LL; step++) {
        // emission loads for all 8 sentence-pairs (L2; hidden under matvec)
        ull em2[8];
#pragma unroll
        for (int sp = 0; sp < 8; sp++) {
            int w0 = wflat[(2 * sp) * LL + step];
            int w1 = wflat[(2 * sp + 1) * LL + step];
            float e0 = __ldg(g_Bt + (size_t)w0 * KT + j);
            float e1 = __ldg(g_Bt + (size_t)w1 * KT + j);
            em2[sp] = pack2(e0, e1);
        }

        // q[j][s-pair] = sum_i p[i][s-pair] * a[i]
        ull q2[8];
#pragma unroll
        for (int sp = 0; sp < 8; sp++) q2[sp] = 0ull;
        const ull (*pc)[KT] = ps[buf];
#pragma unroll
        for (int t = 0; t < 32; t++) {
            ull a0 = packdup(a[2 * t]);
            ull a1 = packdup(a[2 * t + 1]);
#pragma unroll
            for (int sp = 0; sp < 8; sp++) {
                ulonglong2 pp = *(const ulonglong2*)&pc[sp][2 * t];
                q2[sp] = fma2(a0, pp.x, q2[sp]);
                q2[sp] = fma2(a1, pp.y, q2[sp]);
            }
        }

#pragma unroll
        for (int sp = 0; sp < 8; sp++) pn[sp] = mul2(q2[sp], em2[sp]);

        if ((step & 15) == 15) {   // exact per-sentence rescale
#pragma unroll
            for (int sp = 0; sp < 8; sp++) {
                float f0, f1;
                unpack2(pn[sp], f0, f1);
#pragma unroll
                for (int d = 16; d; d >>= 1) {
                    f0 = fmaxf(f0, __shfl_xor_sync(0xffffffffu, f0, d));
                    f1 = fmaxf(f1, __shfl_xor_sync(0xffffffffu, f1, d));
                }
                if (l == 0) exch[w][sp] = make_float2(f0, f1);
            }
            __syncthreads();
#pragma unroll
            for (int sp = 0; sp < 8; sp++) {
                float2 m0 = exch[0][sp], m1 = exch[1][sp];
                float pm0 = fmaxf(m0.x, m1.x);
                float pm1 = fmaxf(m0.y, m1.y);
                int e0 = 0, e1 = 0;
                if (pm0 > 0.f) e0 = ((__float_as_int(pm0) >> 23) & 255) - 126;
                if (pm1 > 0.f) e1 = ((__float_as_int(pm1) >> 23) & 255) - 126;
                S[2 * sp] += e0;
                S[2 * sp + 1] += e1;
                ull sc2 = pack2(__int_as_float((127 - e0) << 23),
                                __int_as_float((127 - e1) << 23));
                pn[sp] = mul2(pn[sp], sc2);
            }
            __syncthreads();   // exch reusable; also orders before stores race-free
        }

        int nb = buf ^ 1;
#pragma unroll
        for (int sp = 0; sp < 8; sp++) ps[nb][sp][j] = pn[sp];
        __syncthreads();
        buf = nb;
    }

    // final transition into EOS with RAW A column; compensate fold exponent
    ull ae = packdup(aeos);
#pragma unroll
    for (int sp = 0; sp < 8; sp++) {
        float s0, s1;
        unpack2(mul2(pn[sp], ae), s0, s1);
#pragma unroll
        for (int d = 16; d; d >>= 1) {
            s0 += __shfl_xor_sync(0xffffffffu, s0, d);
            s1 += __shfl_xor_sync(0xffffffffu, s1, d);
        }
        if (l == 0) exch[w][sp] = make_float2(s0, s1);
    }
    __syncthreads();
    if (tid < 8) {
        int sp = tid;
        float2 x0 = exch[0][sp], x1 = exch[1][sp];
        const float LN2 = 0.6931471805599453f;
        out[sbase + 2 * sp] =
            __logf(x0.x + x1.x) + (float)(S[2 * sp] - LL * FOLD_LOG2) * LN2;
        out[sbase + 2 * sp + 1] =
            __logf(x0.y + x1.y) + (float)(S[2 * sp + 1] - LL * FOLD_LOG2) * LN2;
    }
}

// ---------------------------------------------------------------------------
extern "C" void kernel_launch(void* const* d_in, const int* in_sizes, int n_in,
                              void* d_out, int out_size) {
    const int* words = nullptr;
    const float* ThetaB = nullptr;
    const float* WA = nullptr;
    const float* E = nullptr;
    for (int i = 0; i < n_in; i++) {
        switch (in_sizes[i]) {
            case BB * LL:   words  = (const int*)d_in[i];   break;
            case KT * DD:   ThetaB = (const float*)d_in[i]; break;
            case KT * KT:   WA     = (const float*)d_in[i]; break;
            case VV * DD:   E      = (const float*)d_in[i]; break;
            default: break;
        }
    }

    k_trans<<<1, 256>>>(WA);
    k_emit<<<(VV + 63) / 64, 256>>>(ThetaB, E);
    k_scaleA<<<16, 256>>>();
    k_forward<<<BB / 16, 64>>>(words, (float*)d_out);
}

// round 10
// speedup vs baseline: 1.1407x; 1.0499x over previous
#include <cuda_runtime.h>
#include <math.h>
#include <stdint.h>

#define KT 64
#define VV 50000
#define DD 128
#define BB 8192
#define LL 126
#define BOS 62
#define EOS 63
#define FOLD 32768.0f          // 2^15 folded into scaled A (anti-underflow)
#define FOLD_LOG2 15
#define SPB 4                  // sentence-pairs per block (8 sentences)

typedef unsigned long long ull;

// Scratch (static __device__ — no allocations allowed)
__device__ float g_A[KT * KT];           // raw transition probs (row softmax of WA, col BOS = 0)
__device__ float g_Ast[KT * KT];         // transposed: g_Ast[j*64+i] = A[i][j] * invZ[j] * 2^15
__device__ float g_Z[KT];                // per-tag emission partition sums
__device__ float g_Bt[(size_t)VV * KT];  // exp(theta_k . E_v), layout [v][k] (256B rows)

// ---- packed f32x2 helpers ---------------------------------------------------
__device__ __forceinline__ ull fma2(ull a, ull b, ull c) {
    ull d;
    asm("fma.rn.f32x2 %0, %1, %2, %3;" : "=l"(d) : "l"(a), "l"(b), "l"(c));
    return d;
}
__device__ __forceinline__ ull mul2(ull a, ull b) {
    ull d;
    asm("mul.rn.f32x2 %0, %1, %2;" : "=l"(d) : "l"(a), "l"(b));
    return d;
}
__device__ __forceinline__ ull packdup(float x) {
    ull d;
    asm("mov.b64 %0, {%1, %1};" : "=l"(d) : "f"(x));
    return d;
}
__device__ __forceinline__ ull pack2(float lo, float hi) {
    ull d;
    asm("mov.b64 %0, {%1, %2};" : "=l"(d) : "f"(lo), "f"(hi));
    return d;
}
__device__ __forceinline__ void unpack2(ull v, float& lo, float& hi) {
    asm("mov.b64 {%0, %1}, %2;" : "=f"(lo), "=f"(hi) : "l"(v));
}

// ---------------------------------------------------------------------------
// Kernel 1: transition softmax, warp-per-row; zero Z accumulators.
// Block = 1024 threads = 32 warps; 2 blocks cover 64 rows.
// ---------------------------------------------------------------------------
__global__ void __launch_bounds__(1024) k_trans(const float* __restrict__ WA) {
    int warp = (blockIdx.x * 32) + (threadIdx.x >> 5);   // row i
    int l = threadIdx.x & 31;
    if (warp < KT) {
        const float* row = WA + warp * KT;
        float x0 = row[l];
        float x1 = (32 + l == BOS) ? -1e30f : row[32 + l];   // mask BOS column
        float m = fmaxf(x0, x1);
#pragma unroll
        for (int d = 16; d; d >>= 1) m = fmaxf(m, __shfl_xor_sync(0xffffffffu, m, d));
        float e0 = __expf(x0 - m);
        float e1 = __expf(x1 - m);
        float s = e0 + e1;
#pragma unroll
        for (int d = 16; d; d >>= 1) s += __shfl_xor_sync(0xffffffffu, s, d);
        float inv = 1.f / s;
        g_A[warp * KT + l] = e0 * inv;
        g_A[warp * KT + 32 + l] = (32 + l == BOS) ? 0.f : e1 * inv;
        if (l == 0) g_Z[warp] = 0.f;
    }
}

// ---------------------------------------------------------------------------
// Kernel 2: emission table  g_Bt[v][k] = exp(theta_k . E_v), accumulate Z[k].
// Both fma2 operands packed over d-pairs; theta staged transposed in smem.
// ---------------------------------------------------------------------------
__global__ void __launch_bounds__(256) k_emit(const float* __restrict__ ThetaB,
                                              const float* __restrict__ E) {
    __shared__ ull thsh[DD / 2][KT];     // [d2][k]
    __shared__ float zsh[4][KT];
    int tid = threadIdx.x;
    int k  = tid & 63;
    int vg = tid >> 6;
    for (int idx = tid; idx < KT * DD / 2; idx += 256) {
        int kk = idx >> 6, d2 = idx & 63;
        thsh[d2][kk] = ((const ull*)ThetaB)[kk * (DD / 2) + d2];
    }
    __syncthreads();

    float zacc = 0.f;
    int vbase = blockIdx.x * 64 + vg * 16;
    if (vbase < VV) {
#pragma unroll
        for (int vc = 0; vc < 4; vc++) {
            int v0 = vbase + vc * 4;
            const ulonglong2* E0 = (const ulonglong2*)(E + (size_t)(v0 + 0) * DD);
            const ulonglong2* E1 = (const ulonglong2*)(E + (size_t)(v0 + 1) * DD);
            const ulonglong2* E2 = (const ulonglong2*)(E + (size_t)(v0 + 2) * DD);
            const ulonglong2* E3 = (const ulonglong2*)(E + (size_t)(v0 + 3) * DD);
            ull a0 = 0, a1 = 0, b0 = 0, b1 = 0, c0 = 0, c1 = 0, d0 = 0, d1 = 0;
#pragma unroll 8
            for (int d4 = 0; d4 < DD / 4; d4++) {
                ull t0 = thsh[2 * d4][k];
                ull t1 = thsh[2 * d4 + 1][k];
                ulonglong2 ea = __ldg(E0 + d4);
                ulonglong2 eb = __ldg(E1 + d4);
                ulonglong2 ec = __ldg(E2 + d4);
                ulonglong2 ed = __ldg(E3 + d4);
                a0 = fma2(t0, ea.x, a0); a1 = fma2(t1, ea.y, a1);
                b0 = fma2(t0, eb.x, b0); b1 = fma2(t1, eb.y, b1);
                c0 = fma2(t0, ec.x, c0); c1 = fma2(t1, ec.y, c1);
                d0 = fma2(t0, ed.x, d0); d1 = fma2(t1, ed.y, d1);
            }
            float x0, x1, y0, y1;
            unpack2(a0, x0, x1); unpack2(a1, y0, y1);
            float p0 = __expf((x0 + y0) + (x1 + y1));
            unpack2(b0, x0, x1); unpack2(b1, y0, y1);
            float p1 = __expf((x0 + y0) + (x1 + y1));
            unpack2(c0, x0, x1); unpack2(c1, y0, y1);
            float p2 = __expf((x0 + y0) + (x1 + y1));
            unpack2(d0, x0, x1); unpack2(d1, y0, y1);
            float p3 = __expf((x0 + y0) + (x1 + y1));
            g_Bt[(size_t)(v0 + 0) * KT + k] = p0;
            g_Bt[(size_t)(v0 + 1) * KT + k] = p1;
            g_Bt[(size_t)(v0 + 2) * KT + k] = p2;
            g_Bt[(size_t)(v0 + 3) * KT + k] = p3;
            zacc += (p0 + p1) + (p2 + p3);
        }
    }
    zsh[vg][k] = zacc;
    __syncthreads();
    if (vg == 0)
        atomicAdd(&g_Z[k], (zsh[0][k] + zsh[1][k]) + (zsh[2][k] + zsh[3][k]));
}

// ---------------------------------------------------------------------------
// Kernel 3: build g_Ast[j*64+i] = A[i][j] * invZ[j] * 2^15. BOS/EOS cols -> 0.
// ---------------------------------------------------------------------------
__global__ void __launch_bounds__(256) k_scaleA() {
    int idx = blockIdx.x * 256 + threadIdx.x;
    if (idx < KT * KT) {
        int i = idx >> 6, j = idx & 63;
        float iz = (j >= BOS) ? 0.f : (FOLD / g_Z[j]);
        g_Ast[j * KT + i] = g_A[i * KT + j] * iz;
    }
}

// ---------------------------------------------------------------------------
// Kernel 4: forward recursion. Thread j owns transition column j IN
// REGISTERS (a[64], invZ+2^15 folded). 8 sentences/block as 4 packed pairs;
// GRID = 1024 -> ~6.9 blocks/SM (13.8 warps, 3.46/SMSP): latency hidden,
// fma pipe binding. Per step/warp: 128 broadcast LDS.128 (p pairs) +
// 256 fma.rn.f32x2 + 64 dup movs + 8 LDG. Stores conflict-free.
// Exact per-sentence power-of-two rescale every 16 steps.
// ---------------------------------------------------------------------------
__global__ void __launch_bounds__(64, 8) k_forward(const int* __restrict__ words,
                                                   float* __restrict__ out) {
    __shared__ __align__(16) ull ps[2][SPB][KT];  // [buf][sent-pair][prev-tag]
    __shared__ int wflat[2 * SPB * LL];
    __shared__ float2 exch[2][SPB];
    int tid = threadIdx.x;
    int w   = tid >> 5;
    int l   = tid & 31;
    int j   = tid;            // owned column/tag

    // A column into registers (contiguous row of g_Ast)
    float a[KT];
    {
        const float4* ar = (const float4*)(g_Ast + j * KT);
#pragma unroll
        for (int t = 0; t < 16; t++) {
            float4 v = ar[t];
            a[4 * t] = v.x; a[4 * t + 1] = v.y; a[4 * t + 2] = v.z; a[4 * t + 3] = v.w;
        }
    }
    float aeos = g_A[j * KT + EOS];

    int sbase = blockIdx.x * (2 * SPB);
    const int* wsrc = words + (size_t)sbase * LL;
    for (int idx = tid; idx < 2 * SPB * LL; idx += 64) wflat[idx] = wsrc[idx];

    // initial p: one-hot at BOS (both sentences of a pair identical)
    for (int idx = tid; idx < SPB * KT; idx += 64) {
        int i = idx & 63;
        ps[0][idx >> 6][i] = (i == BOS) ? packdup(1.f) : 0ull;
    }
    __syncthreads();

    int S[2 * SPB];
#pragma unroll
    for (int c = 0; c < 2 * SPB; c++) S[c] = 0;
    int buf = 0;
    ull pn[SPB];

    for (int step = 0; step < LL; step++) {
        // emission loads (L2 gather, hidden under matvec)
        ull em2[SPB];
#pragma unroll
        for (int sp = 0; sp < SPB; sp++) {
            int w0 = wflat[(2 * sp) * LL + step];
            int w1 = wflat[(2 * sp + 1) * LL + step];
            float e0 = __ldg(g_Bt + (size_t)w0 * KT + j);
            float e1 = __ldg(g_Bt + (size_t)w1 * KT + j);
            em2[sp] = pack2(e0, e1);
        }

        // q[j][s-pair] = sum_i p[i][s-pair] * a[i]
        ull q2[SPB];
#pragma unroll
        for (int sp = 0; sp < SPB; sp++) q2[sp] = 0ull;
        const ull (*pc)[KT] = ps[buf];
#pragma unroll
        for (int t = 0; t < 32; t++) {
            ull a0 = packdup(a[2 * t]);
            ull a1 = packdup(a[2 * t + 1]);
#pragma unroll
            for (int sp = 0; sp < SPB; sp++) {
                ulonglong2 pp = *(const ulonglong2*)&pc[sp][2 * t];
                q2[sp] = fma2(a0, pp.x, q2[sp]);
                q2[sp] = fma2(a1, pp.y, q2[sp]);
            }
        }

#pragma unroll
        for (int sp = 0; sp < SPB; sp++) pn[sp] = mul2(q2[sp], em2[sp]);

        if ((step & 15) == 15) {   // exact per-sentence rescale
#pragma unroll
            for (int sp = 0; sp < SPB; sp++) {
                float f0, f1;
                unpack2(pn[sp], f0, f1);
#pragma unroll
                for (int d = 16; d; d >>= 1) {
                    f0 = fmaxf(f0, __shfl_xor_sync(0xffffffffu, f0, d));
                    f1 = fmaxf(f1, __shfl_xor_sync(0xffffffffu, f1, d));
                }
                if (l == 0) exch[w][sp] = make_float2(f0, f1);
            }
            __syncthreads();
#pragma unroll
            for (int sp = 0; sp < SPB; sp++) {
                float2 m0 = exch[0][sp], m1 = exch[1][sp];
                float pm0 = fmaxf(m0.x, m1.x);
                float pm1 = fmaxf(m0.y, m1.y);
                int e0 = 0, e1 = 0;
                if (pm0 > 0.f) e0 = ((__float_as_int(pm0) >> 23) & 255) - 126;
                if (pm1 > 0.f) e1 = ((__float_as_int(pm1) >> 23) & 255) - 126;
                S[2 * sp] += e0;
                S[2 * sp + 1] += e1;
                ull sc2 = pack2(__int_as_float((127 - e0) << 23),
                                __int_as_float((127 - e1) << 23));
                pn[sp] = mul2(pn[sp], sc2);
            }
            __syncthreads();
        }

        int nb = buf ^ 1;
#pragma unroll
        for (int sp = 0; sp < SPB; sp++) ps[nb][sp][j] = pn[sp];
        __syncthreads();
        buf = nb;
    }

    // final transition into EOS with RAW A column; compensate fold exponent
    ull ae = packdup(aeos);
#pragma unroll
    for (int sp = 0; sp < SPB; sp++) {
        float s0, s1;
        unpack2(mul2(pn[sp], ae), s0, s1);
#pragma unroll
        for (int d = 16; d; d >>= 1) {
            s0 += __shfl_xor_sync(0xffffffffu, s0, d);
            s1 += __shfl_xor_sync(0xffffffffu, s1, d);
        }
        if (l == 0) exch[w][sp] = make_float2(s0, s1);
    }
    __syncthreads();
    if (tid < SPB) {
        int sp = tid;
        float2 x0 = exch[0][sp], x1 = exch[1][sp];
        const float LN2 = 0.6931471805599453f;
        out[sbase + 2 * sp] =
            __logf(x0.x + x1.x) + (float)(S[2 * sp] - LL * FOLD_LOG2) * LN2;
        out[sbase + 2 * sp + 1] =
            __logf(x0.y + x1.y) + (float)(S[2 * sp + 1] - LL * FOLD_LOG2) * LN2;
    }
}

// ---------------------------------------------------------------------------
extern "C" void kernel_launch(void* const* d_in, const int* in_sizes, int n_in,
                              void* d_out, int out_size) {
    const int* words = nullptr;
    const float* ThetaB = nullptr;
    const float* WA = nullptr;
    const float* E = nullptr;
    for (int i = 0; i < n_in; i++) {
        switch (in_sizes[i]) {
            case BB * LL:   words  = (const int*)d_in[i];   break;
            case KT * DD:   ThetaB = (const float*)d_in[i]; break;
            case KT * KT:   WA     = (const float*)d_in[i]; break;
            case VV * DD:   E      = (const float*)d_in[i]; break;
            default: break;
        }
    }

    k_trans<<<2, 1024>>>(WA);
    k_emit<<<(VV + 63) / 64, 256>>>(ThetaB, E);
    k_scaleA<<<16, 256>>>();
    k_forward<<<BB / (2 * SPB), 64>>>(words, (float*)d_out);
}

// round 12
// speedup vs baseline: 1.3420x; 1.1765x over previous
#include <cuda_runtime.h>
#include <math.h>
#include <stdint.h>

#define KT 64
#define VV 50000
#define DD 128
#define BB 8192
#define LL 126
#define BOS 62
#define EOS 63
#define FOLD 32768.0f          // 2^15 folded into scaled A (anti-underflow)
#define FOLD_LOG2 15
#define SW 8                   // sentences per warp/block

typedef unsigned long long ull;

// Scratch (static __device__ — no allocations allowed)
__device__ float g_A[KT * KT];           // raw transition probs (row softmax of WA, col BOS = 0)
__device__ float g_Ast[KT * KT];         // g_Ast[j*64+i] = A[i][j] * invZ[j] * 2^15
__device__ float g_Aeos[KT];             // raw A[:, EOS]
__device__ float g_Z[KT];                // per-tag emission partition sums
__device__ float g_Bt[(size_t)VV * KT];  // exp(theta_k . E_v), layout [v][k] (256B rows)

// ---- packed f32x2 helpers ---------------------------------------------------
__device__ __forceinline__ ull fma2(ull a, ull b, ull c) {
    ull d;
    asm("fma.rn.f32x2 %0, %1, %2, %3;" : "=l"(d) : "l"(a), "l"(b), "l"(c));
    return d;
}
__device__ __forceinline__ ull add2(ull a, ull b) {
    ull d;
    asm("add.rn.f32x2 %0, %1, %2;" : "=l"(d) : "l"(a), "l"(b));
    return d;
}
__device__ __forceinline__ void unpack2(ull v, float& lo, float& hi) {
    asm("mov.b64 {%0, %1}, %2;" : "=f"(lo), "=f"(hi) : "l"(v));
}

// ---------------------------------------------------------------------------
// Kernel 1: transition softmax, warp-per-row; zero Z accumulators.
// ---------------------------------------------------------------------------
__global__ void __launch_bounds__(1024) k_trans(const float* __restrict__ WA) {
    int warp = (blockIdx.x * 32) + (threadIdx.x >> 5);   // row i
    int l = threadIdx.x & 31;
    if (warp < KT) {
        const float* row = WA + warp * KT;
        float x0 = row[l];
        float x1 = (32 + l == BOS) ? -1e30f : row[32 + l];   // mask BOS column
        float m = fmaxf(x0, x1);
#pragma unroll
        for (int d = 16; d; d >>= 1) m = fmaxf(m, __shfl_xor_sync(0xffffffffu, m, d));
        float e0 = __expf(x0 - m);
        float e1 = __expf(x1 - m);
        float s = e0 + e1;
#pragma unroll
        for (int d = 16; d; d >>= 1) s += __shfl_xor_sync(0xffffffffu, s, d);
        float inv = 1.f / s;
        g_A[warp * KT + l] = e0 * inv;
        g_A[warp * KT + 32 + l] = (32 + l == BOS) ? 0.f : e1 * inv;
        if (l == 0) g_Z[warp] = 0.f;
    }
}

// ---------------------------------------------------------------------------
// Kernel 2: emission table  g_Bt[v][k] = exp(theta_k . E_v), accumulate Z[k].
// ---------------------------------------------------------------------------
__global__ void __launch_bounds__(256) k_emit(const float* __restrict__ ThetaB,
                                              const float* __restrict__ E) {
    __shared__ ull thsh[DD / 2][KT];     // [d2][k]
    __shared__ float zsh[4][KT];
    int tid = threadIdx.x;
    int k  = tid & 63;
    int vg = tid >> 6;
    for (int idx = tid; idx < KT * DD / 2; idx += 256) {
        int kk = idx >> 6, d2 = idx & 63;
        thsh[d2][kk] = ((const ull*)ThetaB)[kk * (DD / 2) + d2];
    }
    __syncthreads();

    float zacc = 0.f;
    int vbase = blockIdx.x * 64 + vg * 16;
    if (vbase < VV) {
#pragma unroll
        for (int vc = 0; vc < 4; vc++) {
            int v0 = vbase + vc * 4;
            const ulonglong2* E0 = (const ulonglong2*)(E + (size_t)(v0 + 0) * DD);
            const ulonglong2* E1 = (const ulonglong2*)(E + (size_t)(v0 + 1) * DD);
            const ulonglong2* E2 = (const ulonglong2*)(E + (size_t)(v0 + 2) * DD);
            const ulonglong2* E3 = (const ulonglong2*)(E + (size_t)(v0 + 3) * DD);
            ull a0 = 0, a1 = 0, b0 = 0, b1 = 0, c0 = 0, c1 = 0, d0 = 0, d1 = 0;
#pragma unroll 8
            for (int d4 = 0; d4 < DD / 4; d4++) {
                ull t0 = thsh[2 * d4][k];
                ull t1 = thsh[2 * d4 + 1][k];
                ulonglong2 ea = __ldg(E0 + d4);
                ulonglong2 eb = __ldg(E1 + d4);
                ulonglong2 ec = __ldg(E2 + d4);
                ulonglong2 ed = __ldg(E3 + d4);
                a0 = fma2(t0, ea.x, a0); a1 = fma2(t1, ea.y, a1);
                b0 = fma2(t0, eb.x, b0); b1 = fma2(t1, eb.y, b1);
                c0 = fma2(t0, ec.x, c0); c1 = fma2(t1, ec.y, c1);
                d0 = fma2(t0, ed.x, d0); d1 = fma2(t1, ed.y, d1);
            }
            float x0, x1, y0, y1;
            unpack2(a0, x0, x1); unpack2(a1, y0, y1);
            float p0 = __expf((x0 + y0) + (x1 + y1));
            unpack2(b0, x0, x1); unpack2(b1, y0, y1);
            float p1 = __expf((x0 + y0) + (x1 + y1));
            unpack2(c0, x0, x1); unpack2(c1, y0, y1);
            float p2 = __expf((x0 + y0) + (x1 + y1));
            unpack2(d0, x0, x1); unpack2(d1, y0, y1);
            float p3 = __expf((x0 + y0) + (x1 + y1));
            g_Bt[(size_t)(v0 + 0) * KT + k] = p0;
            g_Bt[(size_t)(v0 + 1) * KT + k] = p1;
            g_Bt[(size_t)(v0 + 2) * KT + k] = p2;
            g_Bt[(size_t)(v0 + 3) * KT + k] = p3;
            zacc += (p0 + p1) + (p2 + p3);
        }
    }
    zsh[vg][k] = zacc;
    __syncthreads();
    if (vg == 0)
        atomicAdd(&g_Z[k], (zsh[0][k] + zsh[1][k]) + (zsh[2][k] + zsh[3][k]));
}

// ---------------------------------------------------------------------------
// Kernel 3: g_Ast[j*64+i] = A[i][j]*invZ[j]*2^15 (BOS/EOS cols 0); g_Aeos.
// ---------------------------------------------------------------------------
__global__ void __launch_bounds__(256) k_scaleA() {
    int idx = blockIdx.x * 256 + threadIdx.x;
    if (idx < KT * KT) {
        int i = idx >> 6, j = idx & 63;
        float iz = (j >= BOS) ? 0.f : (FOLD / g_Z[j]);
        g_Ast[j * KT + i] = g_A[i * KT + j] * iz;
    }
    if (blockIdx.x == 0 && threadIdx.x < KT)
        g_Aeos[threadIdx.x] = g_A[threadIdx.x * KT + EOS];
}

// ---------------------------------------------------------------------------
// Kernel 4: forward recursion, single-warp blocks, grid 1024 (single wave).
// Lane l owns transition columns l and l+32 IN REGISTERS as u64 i-pairs
// (a0/a1[32]; invZ * 2^15 folded) -> BOTH fma2 operands naturally packed:
// no dup movs anywhere. 8 sentences per warp, processed sequentially per
// step; p in warp-private double-buffered smem rows (68-float stride).
// Per sentence-step: 16 broadcast LDS.128 (p i-pairs) + 64 fma2 (4 acc
// chains/col, ILP 8) + ~12 finalize + 2 coalesced LDG (em) + 2 STS.32
// (conflict-free). No block barriers — __syncwarp only.
// Per-lane... per-sentence power-of-two rescale every 16 steps (needs one
// 5-round shfl max-reduce; S replicated in all lanes).
// ---------------------------------------------------------------------------
__global__ void __launch_bounds__(32) k_forward(const int* __restrict__ words,
                                                float* __restrict__ out) {
    __shared__ __align__(16) float ps[2][SW][68];   // [buf][sent][tag(64)+pad]
    __shared__ int wflat[SW * LL];
    int l = threadIdx.x;

    // A columns l and l+32 into registers as i-pair u64s
    ull a0[32], a1[32];
    {
        const ull* apl = (const ull*)(g_Ast + (size_t)l * KT);
        const ull* aph = (const ull*)(g_Ast + (size_t)(l + 32) * KT);
#pragma unroll
        for (int t = 0; t < 32; t++) { a0[t] = apl[t]; a1[t] = aph[t]; }
    }
    float aeos0 = g_Aeos[l];
    float aeos1 = g_Aeos[l + 32];

    int sbase = blockIdx.x * SW;
    const int* wsrc = words + (size_t)sbase * LL;
    for (int idx = l; idx < SW * LL; idx += 32) wflat[idx] = wsrc[idx];

    // initial p: one-hot at BOS
    for (int idx = l; idx < SW * 68; idx += 32) {
        int s = idx / 68, tg = idx % 68;
        ps[0][s][tg] = (tg == BOS) ? 1.f : 0.f;
    }
    __syncwarp();

    int S[SW];
#pragma unroll
    for (int s = 0; s < SW; s++) S[s] = 0;
    int buf = 0;

    for (int step = 0; step < LL; step++) {
        // prefetch emissions for all sentences (coalesced 2x128B per sentence)
        float em0[SW], em1[SW];
#pragma unroll
        for (int s = 0; s < SW; s++) {
            int wv = wflat[s * LL + step];
            const float* eb = g_Bt + (size_t)wv * KT;
            em0[s] = __ldg(eb + l);
            em1[s] = __ldg(eb + l + 32);
        }

        int nb = buf ^ 1;
#pragma unroll
        for (int s = 0; s < SW; s++) {
            const ulonglong2* pp = (const ulonglong2*)ps[buf][s];
            ull c0e = 0, c0o = 0, c1e = 0, c1o = 0;
#pragma unroll
            for (int t = 0; t < 16; t++) {
                ulonglong2 pv = pp[t];          // broadcast: i-pairs 2t, 2t+1
                c0e = fma2(a0[2 * t],     pv.x, c0e);
                c0o = fma2(a0[2 * t + 1], pv.y, c0o);
                c1e = fma2(a1[2 * t],     pv.x, c1e);
                c1o = fma2(a1[2 * t + 1], pv.y, c1o);
            }
            float q0lo, q0hi, q1lo, q1hi;
            unpack2(add2(c0e, c0o), q0lo, q0hi);
            unpack2(add2(c1e, c1o), q1lo, q1hi);
            float q0 = (q0lo + q0hi) * em0[s];
            float q1 = (q1lo + q1hi) * em1[s];

            if ((step & 15) == 15) {    // per-sentence rescale
                float pm = fmaxf(q0, q1);
#pragma unroll
                for (int d = 16; d; d >>= 1)
                    pm = fmaxf(pm, __shfl_xor_sync(0xffffffffu, pm, d));
                int e = 0;
                if (pm > 0.f) e = ((__float_as_int(pm) >> 23) & 255) - 126;
                S[s] += e;
                float sc = __int_as_float((127 - e) << 23);
                q0 *= sc; q1 *= sc;
            }
            ps[nb][s][l] = q0;
            ps[nb][s][l + 32] = q1;
        }
        __syncwarp();
        buf = nb;
    }

    // final transition into EOS with raw A column
#pragma unroll
    for (int s = 0; s < SW; s++) {
        float z = ps[buf][s][l] * aeos0 + ps[buf][s][l + 32] * aeos1;
#pragma unroll
        for (int d = 16; d; d >>= 1) z += __shfl_xor_sync(0xffffffffu, z, d);
        if (l == 0)
            out[sbase + s] =
                __logf(z) + (float)(S[s] - LL * FOLD_LOG2) * 0.6931471805599453f;
    }
}

// ---------------------------------------------------------------------------
extern "C" void kernel_launch(void* const* d_in, const int* in_sizes, int n_in,
                              void* d_out, int out_size) {
    const int* words = nullptr;
    const float* ThetaB = nullptr;
    const float* WA = nullptr;
    const float* E = nullptr;
    for (int i = 0; i < n_in; i++) {
        switch (in_sizes[i]) {
            case BB * LL:   words  = (const int*)d_in[i];   break;
            case KT * DD:   ThetaB = (const float*)d_in[i]; break;
            case KT * KT:   WA     = (const float*)d_in[i]; break;
            case VV * DD:   E      = (const float*)d_in[i]; break;
            default: break;
        }
    }

    k_trans<<<2, 1024>>>(WA);
    k_emit<<<(VV + 63) / 64, 256>>>(ThetaB, E);
    k_scaleA<<<16, 256>>>();
    k_forward<<<BB / SW, 32>>>(words, (float*)d_out);
}

// round 14
// speedup vs baseline: 2.4116x; 1.7970x over previous
#include <cuda_runtime.h>
#include <math.h>
#include <stdint.h>

#define KT 64
#define VV 50000
#define DD 128
#define BB 8192
#define LL 126
#define BOS 62
#define EOS 63
#define FOLD 32768.0f          // 2^15 folded into scaled A (anti-underflow)
#define FOLD_LOG2 15

typedef unsigned long long ull;

// Scratch (static __device__ — no allocations allowed)
__device__ float g_A[KT * KT];           // raw transition probs (row softmax of WA, col BOS = 0)
__device__ float g_Ast[KT * KT];         // g_Ast[j*64+i] = A[i][j] * invZ[j] * 2^15
__device__ float g_Aeos[KT];             // raw A[:, EOS]
__device__ float g_Z[KT];                // per-tag emission partition sums
__device__ float g_Bt[(size_t)VV * KT];  // exp(theta_k . E_v), layout [v][k] (256B rows)

// ---- packed f32x2 helpers (k_emit) ------------------------------------------
__device__ __forceinline__ ull fma2(ull a, ull b, ull c) {
    ull d;
    asm("fma.rn.f32x2 %0, %1, %2, %3;" : "=l"(d) : "l"(a), "l"(b), "l"(c));
    return d;
}
__device__ __forceinline__ void unpack2(ull v, float& lo, float& hi) {
    asm("mov.b64 {%0, %1}, %2;" : "=f"(lo), "=f"(hi) : "l"(v));
}

// ---- bf16 / mma helpers -----------------------------------------------------
// d = {hi=bf16(hi_src), lo=bf16(lo_src)}
__device__ __forceinline__ uint32_t cvtpack(float hi_src, float lo_src) {
    uint32_t r;
    asm("cvt.rn.bf16x2.f32 %0, %1, %2;" : "=r"(r) : "f"(hi_src), "f"(lo_src));
    return r;
}
// D += A*B for m16n8k16 bf16 -> f32 (C/D in place)
__device__ __forceinline__ void mma_bf16(float* c, const uint32_t* a, const uint32_t* b) {
    asm volatile(
        "mma.sync.aligned.m16n8k16.row.col.f32.bf16.bf16.f32 "
        "{%0,%1,%2,%3}, {%4,%5,%6,%7}, {%8,%9}, {%0,%1,%2,%3};"
        : "+f"(c[0]), "+f"(c[1]), "+f"(c[2]), "+f"(c[3])
        : "r"(a[0]), "r"(a[1]), "r"(a[2]), "r"(a[3]), "r"(b[0]), "r"(b[1]));
}

// ---------------------------------------------------------------------------
// Kernel 1: transition softmax, warp-per-row; zero Z accumulators.
// ---------------------------------------------------------------------------
__global__ void __launch_bounds__(1024) k_trans(const float* __restrict__ WA) {
    int warp = (blockIdx.x * 32) + (threadIdx.x >> 5);   // row i
    int l = threadIdx.x & 31;
    if (warp < KT) {
        const float* row = WA + warp * KT;
        float x0 = row[l];
        float x1 = (32 + l == BOS) ? -1e30f : row[32 + l];   // mask BOS column
        float m = fmaxf(x0, x1);
#pragma unroll
        for (int d = 16; d; d >>= 1) m = fmaxf(m, __shfl_xor_sync(0xffffffffu, m, d));
        float e0 = __expf(x0 - m);
        float e1 = __expf(x1 - m);
        float s = e0 + e1;
#pragma unroll
        for (int d = 16; d; d >>= 1) s += __shfl_xor_sync(0xffffffffu, s, d);
        float inv = 1.f / s;
        g_A[warp * KT + l] = e0 * inv;
        g_A[warp * KT + 32 + l] = (32 + l == BOS) ? 0.f : e1 * inv;
        if (l == 0) g_Z[warp] = 0.f;
    }
}

// ---------------------------------------------------------------------------
// Kernel 2: emission table  g_Bt[v][k] = exp(theta_k . E_v), accumulate Z[k].
// ---------------------------------------------------------------------------
__global__ void __launch_bounds__(256) k_emit(const float* __restrict__ ThetaB,
                                              const float* __restrict__ E) {
    __shared__ ull thsh[DD / 2][KT];     // [d2][k]
    __shared__ float zsh[4][KT];
    int tid = threadIdx.x;
    int k  = tid & 63;
    int vg = tid >> 6;
    for (int idx = tid; idx < KT * DD / 2; idx += 256) {
        int kk = idx >> 6, d2 = idx & 63;
        thsh[d2][kk] = ((const ull*)ThetaB)[kk * (DD / 2) + d2];
    }
    __syncthreads();

    float zacc = 0.f;
    int vbase = blockIdx.x * 64 + vg * 16;
    if (vbase < VV) {
#pragma unroll
        for (int vc = 0; vc < 4; vc++) {
            int v0 = vbase + vc * 4;
            const ulonglong2* E0 = (const ulonglong2*)(E + (size_t)(v0 + 0) * DD);
            const ulonglong2* E1 = (const ulonglong2*)(E + (size_t)(v0 + 1) * DD);
            const ulonglong2* E2 = (const ulonglong2*)(E + (size_t)(v0 + 2) * DD);
            const ulonglong2* E3 = (const ulonglong2*)(E + (size_t)(v0 + 3) * DD);
            ull a0 = 0, a1 = 0, b0 = 0, b1 = 0, c0 = 0, c1 = 0, d0 = 0, d1 = 0;
#pragma unroll 8
            for (int d4 = 0; d4 < DD / 4; d4++) {
                ull t0 = thsh[2 * d4][k];
                ull t1 = thsh[2 * d4 + 1][k];
                ulonglong2 ea = __ldg(E0 + d4);
                ulonglong2 eb = __ldg(E1 + d4);
                ulonglong2 ec = __ldg(E2 + d4);
                ulonglong2 ed = __ldg(E3 + d4);
                a0 = fma2(t0, ea.x, a0); a1 = fma2(t1, ea.y, a1);
                b0 = fma2(t0, eb.x, b0); b1 = fma2(t1, eb.y, b1);
                c0 = fma2(t0, ec.x, c0); c1 = fma2(t1, ec.y, c1);
                d0 = fma2(t0, ed.x, d0); d1 = fma2(t1, ed.y, d1);
            }
            float x0, x1, y0, y1;
            unpack2(a0, x0, x1); unpack2(a1, y0, y1);
            float p0 = __expf((x0 + y0) + (x1 + y1));
            unpack2(b0, x0, x1); unpack2(b1, y0, y1);
            float p1 = __expf((x0 + y0) + (x1 + y1));
            unpack2(c0, x0, x1); unpack2(c1, y0, y1);
            float p2 = __expf((x0 + y0) + (x1 + y1));
            unpack2(d0, x0, x1); unpack2(d1, y0, y1);
            float p3 = __expf((x0 + y0) + (x1 + y1));
            g_Bt[(size_t)(v0 + 0) * KT + k] = p0;
            g_Bt[(size_t)(v0 + 1) * KT + k] = p1;
            g_Bt[(size_t)(v0 + 2) * KT + k] = p2;
            g_Bt[(size_t)(v0 + 3) * KT + k] = p3;
            zacc += (p0 + p1) + (p2 + p3);
        }
    }
    zsh[vg][k] = zacc;
    __syncthreads();
    if (vg == 0)
        atomicAdd(&g_Z[k], (zsh[0][k] + zsh[1][k]) + (zsh[2][k] + zsh[3][k]));
}

// ---------------------------------------------------------------------------
// Kernel 3: g_Ast[j*64+i] = A[i][j]*invZ[j]*2^15 (BOS/EOS cols 0); g_Aeos.
// ---------------------------------------------------------------------------
__global__ void __launch_bounds__(256) k_scaleA() {
    int idx = blockIdx.x * 256 + threadIdx.x;
    if (idx < KT * KT) {
        int i = idx >> 6, j = idx & 63;
        float iz = (j >= BOS) ? 0.f : (FOLD / g_Z[j]);
        g_Ast[j * KT + i] = g_A[i * KT + j] * iz;
    }
    if (blockIdx.x == 0 && threadIdx.x < KT)
        g_Aeos[threadIdx.x] = g_A[threadIdx.x * KT + EOS];
}

// ---------------------------------------------------------------------------
// Kernel 4: forward recursion on mma.sync (HMMA bf16, standard PTX — works
// on compute_103 unlike tcgen05). One warp per block, 16 sentences (M=16),
// grid 512. Per step: q(16x64) = p(16x64) x B~(64x64) as 8 n-tiles x 4
// k-tiles of m16n8k16, B~ fragments STATIC in 64 registers.
// KEY: the C-fragment (m16n8 f32) of two adjacent n-tiles has exactly the
// A-fragment (m16k16) per-lane layout, so step t's output becomes step
// t+1's A operand with 16 cvt.rn.bf16x2.f32 — no shuffles, no smem.
// Emission: per-lane float2 gathers issued at step top (covered by mma).
// Per-sentence power-of-two rescale every 16 steps (quad shfl max).
// ---------------------------------------------------------------------------
__global__ void __launch_bounds__(32) k_forward(const int* __restrict__ words,
                                                float* __restrict__ out) {
    __shared__ int wflat[LL * 16];      // [step][sentence]
    int l = threadIdx.x;
    int q = l >> 2, t = l & 3;
    int sbase = blockIdx.x * 16;
    const int* wsrc = words + (size_t)sbase * LL;
    for (int idx = l; idx < LL * 16; idx += 32) {
        int s = idx & 15, st = idx >> 4;
        wflat[idx] = wsrc[s * LL + st];
    }
    __syncwarp();

    // Static B~ fragments: Bmat[k][n] = g_Ast[n*64 + k]
    // frag (nt, kt): b0=B[kt*16+2t][nt*8+q], b1=[+1], b2=[+8], b3=[+9]
    uint32_t Bf[8][4][2];
#pragma unroll
    for (int nt = 0; nt < 8; nt++)
#pragma unroll
        for (int kt = 0; kt < 4; kt++) {
            const float* col = g_Ast + (size_t)(nt * 8 + q) * KT + kt * 16 + 2 * t;
            Bf[nt][kt][0] = cvtpack(col[1], col[0]);
            Bf[nt][kt][1] = cvtpack(col[9], col[8]);
        }

    // p_0 = onehot(BOS=62): col 62 = 8*7 + 2*3 -> ntile 7, t==3, c0 (row q)
    // and c2 (row q+8)
    float c[8][4];
#pragma unroll
    for (int nt = 0; nt < 8; nt++)
#pragma unroll
        for (int r = 0; r < 4; r++) c[nt][r] = 0.f;
    if (t == 3) { c[7][0] = 1.f; c[7][2] = 1.f; }

    int S0 = 0, S1 = 0;

    for (int step = 0; step < LL; step++) {
        // emission gathers for this step (consumed after the mma chain)
        int w0 = wflat[step * 16 + q];
        int w1 = wflat[step * 16 + 8 + q];
        const float2* r0 = (const float2*)(g_Bt + (size_t)w0 * KT) + t;
        const float2* r1 = (const float2*)(g_Bt + (size_t)w1 * KT) + t;
        float2 emlo[8], emhi[8];
#pragma unroll
        for (int nt = 0; nt < 8; nt++) {
            emlo[nt] = __ldg(r0 + nt * 4);
            emhi[nt] = __ldg(r1 + nt * 4);
        }

        // C -> A fragments (zero-shuffle layout identity)
        uint32_t Af[4][4];
#pragma unroll
        for (int kt = 0; kt < 4; kt++) {
            Af[kt][0] = cvtpack(c[2 * kt][1],     c[2 * kt][0]);
            Af[kt][1] = cvtpack(c[2 * kt][3],     c[2 * kt][2]);
            Af[kt][2] = cvtpack(c[2 * kt + 1][1], c[2 * kt + 1][0]);
            Af[kt][3] = cvtpack(c[2 * kt + 1][3], c[2 * kt + 1][2]);
        }

        // q = p x B~
#pragma unroll
        for (int nt = 0; nt < 8; nt++) {
            c[nt][0] = 0.f; c[nt][1] = 0.f; c[nt][2] = 0.f; c[nt][3] = 0.f;
#pragma unroll
            for (int kt = 0; kt < 4; kt++)
                mma_bf16(c[nt], Af[kt], Bf[nt][kt]);
        }

        // p = q * em
#pragma unroll
        for (int nt = 0; nt < 8; nt++) {
            c[nt][0] *= emlo[nt].x; c[nt][1] *= emlo[nt].y;
            c[nt][2] *= emhi[nt].x; c[nt][3] *= emhi[nt].y;
        }

        if ((step & 15) == 15) {   // per-sentence power-of-two rescale
            float m0 = 0.f, m1 = 0.f;
#pragma unroll
            for (int nt = 0; nt < 8; nt++) {
                m0 = fmaxf(m0, fmaxf(c[nt][0], c[nt][1]));
                m1 = fmaxf(m1, fmaxf(c[nt][2], c[nt][3]));
            }
            m0 = fmaxf(m0, __shfl_xor_sync(0xffffffffu, m0, 1));
            m0 = fmaxf(m0, __shfl_xor_sync(0xffffffffu, m0, 2));
            m1 = fmaxf(m1, __shfl_xor_sync(0xffffffffu, m1, 1));
            m1 = fmaxf(m1, __shfl_xor_sync(0xffffffffu, m1, 2));
            int e0 = 0, e1 = 0;
            if (m0 > 0.f) e0 = ((__float_as_int(m0) >> 23) & 255) - 126;
            if (m1 > 0.f) e1 = ((__float_as_int(m1) >> 23) & 255) - 126;
            S0 += e0; S1 += e1;
            float sc0 = __int_as_float((127 - e0) << 23);
            float sc1 = __int_as_float((127 - e1) << 23);
#pragma unroll
            for (int nt = 0; nt < 8; nt++) {
                c[nt][0] *= sc0; c[nt][1] *= sc0;
                c[nt][2] *= sc1; c[nt][3] *= sc1;
            }
        }
    }

    // final transition into EOS with raw A column
    float z0 = 0.f, z1 = 0.f;
#pragma unroll
    for (int nt = 0; nt < 8; nt++) {
        float a0 = g_Aeos[8 * nt + 2 * t];
        float a1 = g_Aeos[8 * nt + 2 * t + 1];
        z0 = fmaf(c[nt][0], a0, fmaf(c[nt][1], a1, z0));
        z1 = fmaf(c[nt][2], a0, fmaf(c[nt][3], a1, z1));
    }
    z0 += __shfl_xor_sync(0xffffffffu, z0, 1);
    z0 += __shfl_xor_sync(0xffffffffu, z0, 2);
    z1 += __shfl_xor_sync(0xffffffffu, z1, 1);
    z1 += __shfl_xor_sync(0xffffffffu, z1, 2);
    if (t == 0) {
        const float LN2 = 0.6931471805599453f;
        out[sbase + q]     = __logf(z0) + (float)(S0 - LL * FOLD_LOG2) * LN2;
        out[sbase + 8 + q] = __logf(z1) + (float)(S1 - LL * FOLD_LOG2) * LN2;
    }
}

// ---------------------------------------------------------------------------
extern "C" void kernel_launch(void* const* d_in, const int* in_sizes, int n_in,
                              void* d_out, int out_size) {
    const int* words = nullptr;
    const float* ThetaB = nullptr;
    const float* WA = nullptr;
    const float* E = nullptr;
    for (int i = 0; i < n_in; i++) {
        switch (in_sizes[i]) {
            case BB * LL:   words  = (const int*)d_in[i];   break;
            case KT * DD:   ThetaB = (const float*)d_in[i]; break;
            case KT * KT:   WA     = (const float*)d_in[i]; break;
            case VV * DD:   E      = (const float*)d_in[i]; break;
            default: break;
        }
    }

    k_trans<<<2, 1024>>>(WA);
    k_emit<<<(VV + 63) / 64, 256>>>(ThetaB, E);
    k_scaleA<<<16, 256>>>();
    k_forward<<<BB / 16, 32>>>(words, (float*)d_out);
}

// round 16
// speedup vs baseline: 2.8848x; 1.1962x over previous
#include <cuda_runtime.h>
#include <math.h>
#include <stdint.h>

#define KT 64
#define VV 50000
#define DD 128
#define BB 8192
#define LL 126
#define BOS 62
#define EOS 63
#define FOLD 32768.0f          // 2^15 folded into scaled A (anti-underflow)
#define FOLD_LOG2 15

typedef unsigned long long ull;

// Scratch (static __device__ — no allocations allowed)
__device__ float g_A[KT * KT];           // raw transition probs (row softmax of WA, col BOS = 0)
__device__ float g_Ast[KT * KT];         // g_Ast[j*64+i] = A[i][j] * invZ[j] * 2^15
__device__ float g_Aeos[KT];             // raw A[:, EOS]
__device__ float g_Z[KT];                // per-tag emission partition sums
__device__ float g_Bt[(size_t)VV * KT];  // exp(theta_k . E_v), layout [v][k] (256B rows)

// ---- packed f32x2 helpers (k_emit) ------------------------------------------
__device__ __forceinline__ ull fma2(ull a, ull b, ull c) {
    ull d;
    asm("fma.rn.f32x2 %0, %1, %2, %3;" : "=l"(d) : "l"(a), "l"(b), "l"(c));
    return d;
}
__device__ __forceinline__ void unpack2(ull v, float& lo, float& hi) {
    asm("mov.b64 {%0, %1}, %2;" : "=f"(lo), "=f"(hi) : "l"(v));
}

// ---- bf16 / mma helpers -----------------------------------------------------
__device__ __forceinline__ uint32_t cvtpack(float hi_src, float lo_src) {
    uint32_t r;
    asm("cvt.rn.bf16x2.f32 %0, %1, %2;" : "=r"(r) : "f"(hi_src), "f"(lo_src));
    return r;
}
__device__ __forceinline__ void mma_bf16(float* c, const uint32_t* a, const uint32_t* b) {
    asm volatile(
        "mma.sync.aligned.m16n8k16.row.col.f32.bf16.bf16.f32 "
        "{%0,%1,%2,%3}, {%4,%5,%6,%7}, {%8,%9}, {%0,%1,%2,%3};"
        : "+f"(c[0]), "+f"(c[1]), "+f"(c[2]), "+f"(c[3])
        : "r"(a[0]), "r"(a[1]), "r"(a[2]), "r"(a[3]), "r"(b[0]), "r"(b[1]));
}

// ---------------------------------------------------------------------------
// Kernel 1: transition softmax, warp-per-row; zero Z accumulators.
// ---------------------------------------------------------------------------
__global__ void __launch_bounds__(1024) k_trans(const float* __restrict__ WA) {
    int warp = (blockIdx.x * 32) + (threadIdx.x >> 5);   // row i
    int l = threadIdx.x & 31;
    if (warp < KT) {
        const float* row = WA + warp * KT;
        float x0 = row[l];
        float x1 = (32 + l == BOS) ? -1e30f : row[32 + l];   // mask BOS column
        float m = fmaxf(x0, x1);
#pragma unroll
        for (int d = 16; d; d >>= 1) m = fmaxf(m, __shfl_xor_sync(0xffffffffu, m, d));
        float e0 = __expf(x0 - m);
        float e1 = __expf(x1 - m);
        float s = e0 + e1;
#pragma unroll
        for (int d = 16; d; d >>= 1) s += __shfl_xor_sync(0xffffffffu, s, d);
        float inv = 1.f / s;
        g_A[warp * KT + l] = e0 * inv;
        g_A[warp * KT + 32 + l] = (32 + l == BOS) ? 0.f : e1 * inv;
        if (l == 0) g_Z[warp] = 0.f;
    }
}

// ---------------------------------------------------------------------------
// Kernel 2: emission table  g_Bt[v][k] = exp(theta_k . E_v), accumulate Z[k].
// ---------------------------------------------------------------------------
__global__ void __launch_bounds__(256) k_emit(const float* __restrict__ ThetaB,
                                              const float* __restrict__ E) {
    __shared__ ull thsh[DD / 2][KT];     // [d2][k]
    __shared__ float zsh[4][KT];
    int tid = threadIdx.x;
    int k  = tid & 63;
    int vg = tid >> 6;
    for (int idx = tid; idx < KT * DD / 2; idx += 256) {
        int kk = idx >> 6, d2 = idx & 63;
        thsh[d2][kk] = ((const ull*)ThetaB)[kk * (DD / 2) + d2];
    }
    __syncthreads();

    float zacc = 0.f;
    int vbase = blockIdx.x * 64 + vg * 16;
    if (vbase < VV) {
#pragma unroll
        for (int vc = 0; vc < 4; vc++) {
            int v0 = vbase + vc * 4;
            const ulonglong2* E0 = (const ulonglong2*)(E + (size_t)(v0 + 0) * DD);
            const ulonglong2* E1 = (const ulonglong2*)(E + (size_t)(v0 + 1) * DD);
            const ulonglong2* E2 = (const ulonglong2*)(E + (size_t)(v0 + 2) * DD);
            const ulonglong2* E3 = (const ulonglong2*)(E + (size_t)(v0 + 3) * DD);
            ull a0 = 0, a1 = 0, b0 = 0, b1 = 0, c0 = 0, c1 = 0, d0 = 0, d1 = 0;
#pragma unroll 8
            for (int d4 = 0; d4 < DD / 4; d4++) {
                ull t0 = thsh[2 * d4][k];
                ull t1 = thsh[2 * d4 + 1][k];
                ulonglong2 ea = __ldg(E0 + d4);
                ulonglong2 eb = __ldg(E1 + d4);
                ulonglong2 ec = __ldg(E2 + d4);
                ulonglong2 ed = __ldg(E3 + d4);
                a0 = fma2(t0, ea.x, a0); a1 = fma2(t1, ea.y, a1);
                b0 = fma2(t0, eb.x, b0); b1 = fma2(t1, eb.y, b1);
                c0 = fma2(t0, ec.x, c0); c1 = fma2(t1, ec.y, c1);
                d0 = fma2(t0, ed.x, d0); d1 = fma2(t1, ed.y, d1);
            }
            float x0, x1, y0, y1;
            unpack2(a0, x0, x1); unpack2(a1, y0, y1);
            float p0 = __expf((x0 + y0) + (x1 + y1));
            unpack2(b0, x0, x1); unpack2(b1, y0, y1);
            float p1 = __expf((x0 + y0) + (x1 + y1));
            unpack2(c0, x0, x1); unpack2(c1, y0, y1);
            float p2 = __expf((x0 + y0) + (x1 + y1));
            unpack2(d0, x0, x1); unpack2(d1, y0, y1);
            float p3 = __expf((x0 + y0) + (x1 + y1));
            g_Bt[(size_t)(v0 + 0) * KT + k] = p0;
            g_Bt[(size_t)(v0 + 1) * KT + k] = p1;
            g_Bt[(size_t)(v0 + 2) * KT + k] = p2;
            g_Bt[(size_t)(v0 + 3) * KT + k] = p3;
            zacc += (p0 + p1) + (p2 + p3);
        }
    }
    zsh[vg][k] = zacc;
    __syncthreads();
    if (vg == 0)
        atomicAdd(&g_Z[k], (zsh[0][k] + zsh[1][k]) + (zsh[2][k] + zsh[3][k]));
}

// ---------------------------------------------------------------------------
// Kernel 3: g_Ast[j*64+i] = A[i][j]*invZ[j]*2^15 (BOS/EOS cols 0); g_Aeos.
// ---------------------------------------------------------------------------
__global__ void __launch_bounds__(256) k_scaleA() {
    int idx = blockIdx.x * 256 + threadIdx.x;
    if (idx < KT * KT) {
        int i = idx >> 6, j = idx & 63;
        float iz = (j >= BOS) ? 0.f : (FOLD / g_Z[j]);
        g_Ast[j * KT + i] = g_A[i * KT + j] * iz;
    }
    if (blockIdx.x == 0 && threadIdx.x < KT)
        g_Aeos[threadIdx.x] = g_A[threadIdx.x * KT + EOS];
}

// ---------------------------------------------------------------------------
// Kernel 4: forward recursion on mma.sync (HMMA bf16). One warp per block,
// 16 sentences (M=16), grid 512. Per step: q(16x64) = p(16x64) x B~(64x64)
// as 8 n-tiles x 4 k-tiles of m16n8k16, B~ fragments STATIC in registers.
// C-fragment -> A-fragment is a zero-shuffle layout identity (16 cvts).
// R14: emission gathers SOFTWARE-PIPELINED one step ahead (double-buffered
// in registers, loop unrolled x2 so buffer swap is free) — the ~300-600cyc
// L2 gather latency now overlaps the previous step's mma chain instead of
// sitting on the critical path (R13 ncu: issue=8.5%, 1590 cyc/step).
// ---------------------------------------------------------------------------
__global__ void __launch_bounds__(32) k_forward(const int* __restrict__ words,
                                                float* __restrict__ out) {
    __shared__ int wflat[LL * 16];      // [step][sentence]
    int l = threadIdx.x;
    int q = l >> 2, t = l & 3;
    int sbase = blockIdx.x * 16;
    const int* wsrc = words + (size_t)sbase * LL;
    for (int idx = l; idx < LL * 16; idx += 32) {
        int s = idx & 15, st = idx >> 4;
        wflat[idx] = wsrc[s * LL + st];
    }
    __syncwarp();

    // Static B~ fragments: Bmat[k][n] = g_Ast[n*64 + k]
    uint32_t Bf[8][4][2];
#pragma unroll
    for (int nt = 0; nt < 8; nt++)
#pragma unroll
        for (int kt = 0; kt < 4; kt++) {
            const float* col = g_Ast + (size_t)(nt * 8 + q) * KT + kt * 16 + 2 * t;
            Bf[nt][kt][0] = cvtpack(col[1], col[0]);
            Bf[nt][kt][1] = cvtpack(col[9], col[8]);
        }

    // p_0 = onehot(BOS=62): ntile 7, t==3, c0 (row q) and c2 (row q+8)
    float c[8][4];
#pragma unroll
    for (int nt = 0; nt < 8; nt++)
#pragma unroll
        for (int r = 0; r < 4; r++) c[nt][r] = 0.f;
    if (t == 3) { c[7][0] = 1.f; c[7][2] = 1.f; }

    int S0 = 0, S1 = 0;

    // emission double buffers (A and B)
    float2 eAlo[8], eAhi[8], eBlo[8], eBhi[8];

    // prime buffer A with step 0's emissions
    {
        int w0 = wflat[q];
        int w1 = wflat[8 + q];
        const float2* r0 = (const float2*)(g_Bt + (size_t)w0 * KT) + t;
        const float2* r1 = (const float2*)(g_Bt + (size_t)w1 * KT) + t;
#pragma unroll
        for (int nt = 0; nt < 8; nt++) {
            eAlo[nt] = __ldg(r0 + nt * 4);
            eAhi[nt] = __ldg(r1 + nt * 4);
        }
    }

    // One forward step: prefetch step (STEPI+1) into NLO/NHI, then compute
    // step STEPI consuming CLO/CHI.
#define STEP_BODY(STEPI, CLO, CHI, NLO, NHI) do {                              \
        int sn = (STEPI) + 1; if (sn >= LL) sn = LL - 1;                       \
        int w0 = wflat[sn * 16 + q];                                           \
        int w1 = wflat[sn * 16 + 8 + q];                                       \
        const float2* r0 = (const float2*)(g_Bt + (size_t)w0 * KT) + t;        \
        const float2* r1 = (const float2*)(g_Bt + (size_t)w1 * KT) + t;        \
        _Pragma("unroll")                                                      \
        for (int nt = 0; nt < 8; nt++) {                                       \
            NLO[nt] = __ldg(r0 + nt * 4);                                      \
            NHI[nt] = __ldg(r1 + nt * 4);                                      \
        }                                                                      \
        uint32_t Af[4][4];                                                     \
        _Pragma("unroll")                                                      \
        for (int kt = 0; kt < 4; kt++) {                                       \
            Af[kt][0] = cvtpack(c[2 * kt][1],     c[2 * kt][0]);               \
            Af[kt][1] = cvtpack(c[2 * kt][3],     c[2 * kt][2]);               \
            Af[kt][2] = cvtpack(c[2 * kt + 1][1], c[2 * kt + 1][0]);           \
            Af[kt][3] = cvtpack(c[2 * kt + 1][3], c[2 * kt + 1][2]);           \
        }                                                                      \
        _Pragma("unroll")                                                      \
        for (int nt = 0; nt < 8; nt++) {                                       \
            c[nt][0] = 0.f; c[nt][1] = 0.f; c[nt][2] = 0.f; c[nt][3] = 0.f;    \
            _Pragma("unroll")                                                  \
            for (int kt = 0; kt < 4; kt++)                                     \
                mma_bf16(c[nt], Af[kt], Bf[nt][kt]);                           \
        }                                                                      \
        _Pragma("unroll")                                                      \
        for (int nt = 0; nt < 8; nt++) {                                       \
            c[nt][0] *= CLO[nt].x; c[nt][1] *= CLO[nt].y;                      \
            c[nt][2] *= CHI[nt].x; c[nt][3] *= CHI[nt].y;                      \
        }                                                                      \
        if (((STEPI) & 15) == 15) {                                            \
            float m0 = 0.f, m1 = 0.f;                                          \
            _Pragma("unroll")                                                  \
            for (int nt = 0; nt < 8; nt++) {                                   \
                m0 = fmaxf(m0, fmaxf(c[nt][0], c[nt][1]));                     \
                m1 = fmaxf(m1, fmaxf(c[nt][2], c[nt][3]));                     \
            }                                                                  \
            m0 = fmaxf(m0, __shfl_xor_sync(0xffffffffu, m0, 1));               \
            m0 = fmaxf(m0, __shfl_xor_sync(0xffffffffu, m0, 2));               \
            m1 = fmaxf(m1, __shfl_xor_sync(0xffffffffu, m1, 1));               \
            m1 = fmaxf(m1, __shfl_xor_sync(0xffffffffu, m1, 2));               \
            int e0 = 0, e1 = 0;                                                \
            if (m0 > 0.f) e0 = ((__float_as_int(m0) >> 23) & 255) - 126;       \
            if (m1 > 0.f) e1 = ((__float_as_int(m1) >> 23) & 255) - 126;       \
            S0 += e0; S1 += e1;                                                \
            float sc0 = __int_as_float((127 - e0) << 23);                      \
            float sc1 = __int_as_float((127 - e1) << 23);                      \
            _Pragma("unroll")                                                  \
            for (int nt = 0; nt < 8; nt++) {                                   \
                c[nt][0] *= sc0; c[nt][1] *= sc0;                              \
                c[nt][2] *= sc1; c[nt][3] *= sc1;                              \
            }                                                                  \
        }                                                                      \
    } while (0)

    for (int step = 0; step < LL; step += 2) {
        STEP_BODY(step,     eAlo, eAhi, eBlo, eBhi);   // consume A, fill B
        STEP_BODY(step + 1, eBlo, eBhi, eAlo, eAhi);   // consume B, fill A
    }
#undef STEP_BODY

    // final transition into EOS with raw A column
    float z0 = 0.f, z1 = 0.f;
#pragma unroll
    for (int nt = 0; nt < 8; nt++) {
        float a0 = g_Aeos[8 * nt + 2 * t];
        float a1 = g_Aeos[8 * nt + 2 * t + 1];
        z0 = fmaf(c[nt][0], a0, fmaf(c[nt][1], a1, z0));
        z1 = fmaf(c[nt][2], a0, fmaf(c[nt][3], a1, z1));
    }
    z0 += __shfl_xor_sync(0xffffffffu, z0, 1);
    z0 += __shfl_xor_sync(0xffffffffu, z0, 2);
    z1 += __shfl_xor_sync(0xffffffffu, z1, 1);
    z1 += __shfl_xor_sync(0xffffffffu, z1, 2);
    if (t == 0) {
        const float LN2 = 0.6931471805599453f;
        out[sbase + q]     = __logf(z0) + (float)(S0 - LL * FOLD_LOG2) * LN2;
        out[sbase + 8 + q] = __logf(z1) + (float)(S1 - LL * FOLD_LOG2) * LN2;
    }
}

// ---------------------------------------------------------------------------
extern "C" void kernel_launch(void* const* d_in, const int* in_sizes, int n_in,
                              void* d_out, int out_size) {
    const int* words = nullptr;
    const float* ThetaB = nullptr;
    const float* WA = nullptr;
    const float* E = nullptr;
    for (int i = 0; i < n_in; i++) {
        switch (in_sizes[i]) {
            case BB * LL:   words  = (const int*)d_in[i];   break;
            case KT * DD:   ThetaB = (const float*)d_in[i]; break;
            case KT * KT:   WA     = (const float*)d_in[i]; break;
            case VV * DD:   E      = (const float*)d_in[i]; break;
            default: break;
        }
    }

    k_trans<<<2, 1024>>>(WA);
    k_emit<<<(VV + 63) / 64, 256>>>(ThetaB, E);
    k_scaleA<<<16, 256>>>();
    k_forward<<<BB / 16, 32>>>(words, (float*)d_out);
}